// round 10
// baseline (speedup 1.0000x reference)
#include <cuda_runtime.h>

// RNN_33964601377372: h_{t+1} = relu(x_t*W_ih + b_ih + b_hh + W_hh h_t), out = fc(h_T)
//
// Dense geometry: one thread per (batch,row). block=640 = 32 batches x 20 rows,
// grid=128 -> 5 warps per SMSP uniformly (first config with enough warps to
// hide latency; FFMA2 shown rt=2 across rounds, so the pipe floor is
// 5 warps x 24 fma-cyc = 120 cyc/step). h exchanged via CTA shared memory with
// parity double-buffering and ONE __syncthreads per step. Each lane:
// 5x LDS.128 (10 ready f32x2 pairs), 11 FFMA2 + 1 FADD + FMNMX, 1 STS.32.

#define HID 20

typedef unsigned long long u64;

__device__ __forceinline__ u64 pack2(float lo, float hi) {
    u64 r; asm("mov.b64 %0, {%1, %2};" : "=l"(r) : "f"(lo), "f"(hi)); return r;
}
__device__ __forceinline__ u64 dup2(float v) {
    u64 r; asm("mov.b64 %0, {%1, %1};" : "=l"(r) : "f"(v)); return r;
}
__device__ __forceinline__ void unpack2(u64 p, float& lo, float& hi) {
    asm("mov.b64 {%0, %1}, %2;" : "=f"(lo), "=f"(hi) : "l"(p));
}
__device__ __forceinline__ u64 ffma2(u64 a, u64 b, u64 c) {
    u64 d; asm("fma.rn.f32x2 %0, %1, %2, %3;" : "=l"(d) : "l"(a), "l"(b), "l"(c)); return d;
}
__device__ __forceinline__ void lds_v2u64(unsigned addr, u64& a, u64& b) {
    asm volatile("ld.shared.v2.u64 {%0, %1}, [%2];" : "=l"(a), "=l"(b) : "r"(addr));
}
__device__ __forceinline__ void sts_f32(unsigned addr, float v) {
    asm volatile("st.shared.f32 [%0], %1;" :: "r"(addr), "f"(v));
}

#define BATCHES_PER_CTA 32
#define ROW_PAD 24   // floats per h row (96B): conflict-free 16B broadcast reads

__global__ __launch_bounds__(640) void rnn_fused_kernel(
    const float* __restrict__ x,    // [B, T]
    const float* __restrict__ Wih,  // [H]
    const float* __restrict__ Whh,  // [H, H] row-major
    const float* __restrict__ bih,  // [H]
    const float* __restrict__ bhh,  // [H]
    const float* __restrict__ fcw,  // [H]
    const float* __restrict__ fcb,  // [1]
    float* __restrict__ out,        // [B]
    int B, int T)
{
    __shared__ float hbuf[2][BATCHES_PER_CTA][ROW_PAD];

    const int t  = threadIdx.x;            // 0..639
    const int bl = t / HID;                // batch within CTA: 0..31
    const int r  = t - bl * HID;           // row: 0..19
    int batch = blockIdx.x * BATCHES_PER_CTA + bl;
    const bool real = (batch < B);
    if (!real) batch = B - 1;              // clamp; thread must stay for BAR

    // j-packed weights for my row: wJ[k] = (Whh[r][2k], Whh[r][2k+1])
    u64 wJ[10];
#pragma unroll
    for (int k = 0; k < 10; ++k)
        wJ[k] = pack2(Whh[r * HID + 2 * k], Whh[r * HID + 2 * k + 1]);

    // x-projection + bias in the lo half of the seed.
    const u64 wihP  = pack2(Wih[r], 0.0f);
    const u64 biasP = pack2(bih[r] + bhh[r], 0.0f);

    const unsigned rd0 = (unsigned)__cvta_generic_to_shared(&hbuf[0][bl][0]);
    const unsigned rd1 = (unsigned)__cvta_generic_to_shared(&hbuf[1][bl][0]);
    const unsigned wr0 = rd0 + 4u * r;
    const unsigned wr1 = rd1 + 4u * r;

    // h(0) = 0 into buffer 0.
    sts_f32(wr0, 0.0f);
    __syncthreads();

    const float* xb = x + (size_t)batch * T;   // all 20 lanes of a batch share
    const float4* xb4 = (const float4*)xb;     // these addresses (L1 broadcast)
    const int nChunks = T >> 2;

    auto step = [&](float xt, unsigned rd, unsigned wr) {
        u64 hp[10];
#pragma unroll
        for (int i = 0; i < 5; ++i)
            lds_v2u64(rd + 16u * i, hp[2 * i], hp[2 * i + 1]);

        u64 acc = ffma2(dup2(xt), wihP, biasP);
#pragma unroll
        for (int k = 0; k < 10; ++k)
            acc = ffma2(hp[k], wJ[k], acc);

        float lo, hi;
        unpack2(acc, lo, hi);
        sts_f32(wr, fmaxf(lo + hi, 0.0f));
        __syncthreads();   // one BAR/step; parity buffering handles WAR/RAW
    };

    // Deep x prefetch: 2 chunks (8 steps) in flight.
    float4 x0 = make_float4(0.f, 0.f, 0.f, 0.f);
    float4 x1 = x0;
    if (nChunks > 0) x0 = xb4[0];
    if (nChunks > 1) x1 = xb4[1];

    for (int c = 0; c < nChunks; ++c) {
        float4 x2 = x1;
        if (c + 2 < nChunks) x2 = xb4[c + 2];
        step(x0.x, rd0, wr1);
        step(x0.y, rd1, wr0);
        step(x0.z, rd0, wr1);
        step(x0.w, rd1, wr0);
        x0 = x1;
        x1 = x2;
    }
    // Tail (not taken for T=1000): continue parity from step index.
    for (int s = nChunks << 2; s < T; ++s) {
        if (s & 1) step(xb[s], rd1, wr0);
        else       step(xb[s], rd0, wr1);
    }

    // Final h lives in buffer (T & 1). Head: one thread per batch.
    const int fp = T & 1;
    if (t < BATCHES_PER_CTA) {
        int b2 = blockIdx.x * BATCHES_PER_CTA + t;
        if (b2 < B) {
            float s = fcb[0];
#pragma unroll
            for (int rr = 0; rr < HID; ++rr)
                s += hbuf[fp][t][rr] * fcw[rr];
            out[b2] = s;
        }
    }
}

extern "C" void kernel_launch(void* const* d_in, const int* in_sizes, int n_in,
                              void* d_out, int out_size)
{
    const float* x    = (const float*)d_in[0];
    const float* Wih  = (const float*)d_in[1];
    const float* Whh  = (const float*)d_in[2];
    const float* bih  = (const float*)d_in[3];
    const float* bhh  = (const float*)d_in[4];
    const float* fcw  = (const float*)d_in[5];
    const float* fcb  = (const float*)d_in[6];
    float* out = (float*)d_out;

    int B = out_size;
    int T = in_sizes[0] / B;

    const int threads = 640;               // 20 warps -> 5 per SMSP
    int blocks = (B + BATCHES_PER_CTA - 1) / BATCHES_PER_CTA;   // 128 at B=4096
    rnn_fused_kernel<<<blocks, threads>>>(x, Wih, Whh, bih, bhh, fcw, fcb, out, B, T);
}

// round 11
// speedup vs baseline: 1.1980x; 1.1980x over previous
#include <cuda_runtime.h>

// RNN_33964601377372: h_{t+1} = relu(x_t*W_ih + b_ih + b_hh + W_hh h_t), out = fc(h_T)
//
// L=8 row-split x 2 INTERLEAVED batches per 8-lane group. Lane e owns rows
// {e, 8+e, (e<4)?16+e:e} (dummy third row for e>=4 is a harmless duplicate) of
// BOTH batches; the two recurrence chains are independent, so their FFMA2
// streams hide each other's LDS latency inside one warp. W_hh registers are
// shared between chains. h in per-warp smem, no per-step syncs (same-warp
// in-order LSU, validated in R9). Rows padded to 28 floats: all LDS.128
// broadcasts and all STS phases conflict-free mod 32.
// block=128 -> 4 warps, one per SMSP; grid=128 -> 1 CTA/SM; 32 batches/CTA.

#define HID 20

typedef unsigned long long u64;

__device__ __forceinline__ u64 pack2(float lo, float hi) {
    u64 r; asm("mov.b64 %0, {%1, %2};" : "=l"(r) : "f"(lo), "f"(hi)); return r;
}
__device__ __forceinline__ u64 dup2(float v) {
    u64 r; asm("mov.b64 %0, {%1, %1};" : "=l"(r) : "f"(v)); return r;
}
__device__ __forceinline__ void unpack2(u64 p, float& lo, float& hi) {
    asm("mov.b64 {%0, %1}, %2;" : "=f"(lo), "=f"(hi) : "l"(p));
}
__device__ __forceinline__ u64 ffma2(u64 a, u64 b, u64 c) {
    u64 d; asm("fma.rn.f32x2 %0, %1, %2, %3;" : "=l"(d) : "l"(a), "l"(b), "l"(c)); return d;
}
__device__ __forceinline__ void lds_v2u64(unsigned addr, u64& a, u64& b) {
    asm volatile("ld.shared.v2.u64 {%0, %1}, [%2];" : "=l"(a), "=l"(b) : "r"(addr));
}
__device__ __forceinline__ void sts_f32(unsigned addr, float v) {
    asm volatile("st.shared.f32 [%0], %1;" :: "r"(addr), "f"(v));
}
__device__ __forceinline__ float lds_f32(unsigned addr) {
    float v; asm volatile("ld.shared.f32 %0, [%1];" : "=f"(v) : "r"(addr)); return v;
}

#define ROW_PAD 28   // floats per h row (112B): conflict-free reads AND stores

__global__ __launch_bounds__(128) void rnn_fused_kernel(
    const float* __restrict__ x,    // [B, T]
    const float* __restrict__ Wih,  // [H]
    const float* __restrict__ Whh,  // [H, H] row-major
    const float* __restrict__ bih,  // [H]
    const float* __restrict__ bhh,  // [H]
    const float* __restrict__ fcw,  // [H]
    const float* __restrict__ fcb,  // [1]
    float* __restrict__ out,        // [B]
    int B, int T)
{
    // 32 h rows (16 groups x 2 chains) per CTA.
    __shared__ float hbuf[32][ROW_PAD];

    const int lt = threadIdx.x;        // 0..127
    const int g  = lt >> 3;            // group (0..15): handles 2 batches
    const int e  = lt & 7;             // lane within group
    int b0 = blockIdx.x * 32 + 2 * g;  // chain-0 batch
    int b1 = b0 + 1;                   // chain-1 batch
    const bool real0 = (b0 < B);
    const bool real1 = (b1 < B);
    if (!real0) b0 = B - 1;
    if (!real1) b1 = B - 1;

    // Owned rows; lanes e>=4 duplicate row e as third (same value, same addr).
    const int r_[3] = { e, 8 + e, (e < 4) ? 16 + e : e };

    // j-packed weights, SHARED by both chains.
    u64 wJ[3][10];
#pragma unroll
    for (int r = 0; r < 3; ++r)
#pragma unroll
        for (int k = 0; k < 10; ++k)
            wJ[r][k] = pack2(Whh[r_[r] * HID + 2 * k],
                             Whh[r_[r] * HID + 2 * k + 1]);

    u64 wihP[3], biasP[3];
#pragma unroll
    for (int r = 0; r < 3; ++r) {
        wihP[r]  = pack2(Wih[r_[r]], 0.0f);
        biasP[r] = pack2(bih[r_[r]] + bhh[r_[r]], 0.0f);
    }

    const unsigned s0 = (unsigned)__cvta_generic_to_shared(&hbuf[2 * g + 0][0]);
    const unsigned s1 = (unsigned)__cvta_generic_to_shared(&hbuf[2 * g + 1][0]);

    // h(0) = 0 for both chains.
#pragma unroll
    for (int r = 0; r < 3; ++r) {
        sts_f32(s0 + 4u * r_[r], 0.0f);
        sts_f32(s1 + 4u * r_[r], 0.0f);
    }

    const float* xb0 = x + (size_t)b0 * T;
    const float* xb1 = x + (size_t)b1 * T;
    const float4* x4_0 = (const float4*)xb0;
    const float4* x4_1 = (const float4*)xb1;
    const int nChunks = T >> 2;

    // One timestep for BOTH chains, instruction streams interleaved.
    auto step2 = [&](float xt0, float xt1) {
        u64 hp0[10], hp1[10];
#pragma unroll
        for (int i = 0; i < 5; ++i)
            lds_v2u64(s0 + 16u * i, hp0[2 * i], hp0[2 * i + 1]);
#pragma unroll
        for (int i = 0; i < 5; ++i)
            lds_v2u64(s1 + 16u * i, hp1[2 * i], hp1[2 * i + 1]);

        u64 xA = dup2(xt0), xB = dup2(xt1);
        u64 acc0[3], acc1[3];
#pragma unroll
        for (int r = 0; r < 3; ++r) {
            acc0[r] = ffma2(xA, wihP[r], biasP[r]);
            acc1[r] = ffma2(xB, wihP[r], biasP[r]);
        }
#pragma unroll
        for (int k = 0; k < 10; ++k)
#pragma unroll
            for (int r = 0; r < 3; ++r) {
                acc0[r] = ffma2(hp0[k], wJ[r][k], acc0[r]);
                acc1[r] = ffma2(hp1[k], wJ[r][k], acc1[r]);
            }
#pragma unroll
        for (int r = 0; r < 3; ++r) {
            float lo0, hi0, lo1, hi1;
            unpack2(acc0[r], lo0, hi0);
            unpack2(acc1[r], lo1, hi1);
            sts_f32(s0 + 4u * r_[r], fmaxf(lo0 + hi0, 0.0f));
            sts_f32(s1 + 4u * r_[r], fmaxf(lo1 + hi1, 0.0f));
        }
    };

    // Deep x prefetch: 2 chunks (8 steps) per chain in flight.
    float4 a0 = make_float4(0.f, 0.f, 0.f, 0.f), a1 = a0, c0 = a0, c1 = a0;
    if (nChunks > 0) { a0 = x4_0[0]; c0 = x4_1[0]; }
    if (nChunks > 1) { a1 = x4_0[1]; c1 = x4_1[1]; }

    for (int c = 0; c < nChunks; ++c) {
        float4 a2 = a1, c2 = c1;
        if (c + 2 < nChunks) { a2 = x4_0[c + 2]; c2 = x4_1[c + 2]; }
        step2(a0.x, c0.x);
        step2(a0.y, c0.y);
        step2(a0.z, c0.z);
        step2(a0.w, c0.w);
        a0 = a1; a1 = a2;
        c0 = c1; c1 = c2;
    }
    for (int t = nChunks << 2; t < T; ++t)       // tail (unused @T=1000)
        step2(xb0[t], xb1[t]);

    __syncwarp();   // one-time: publish final h for head reads

    // Head for both chains: partials over owned rows, xor-reduce across 8 lanes.
    float p0 = lds_f32(s0 + 4u * r_[0]) * fcw[r_[0]]
             + lds_f32(s0 + 4u * r_[1]) * fcw[r_[1]];
    float p1 = lds_f32(s1 + 4u * r_[0]) * fcw[r_[0]]
             + lds_f32(s1 + 4u * r_[1]) * fcw[r_[1]];
    if (e < 4) {
        p0 += lds_f32(s0 + 4u * r_[2]) * fcw[r_[2]];
        p1 += lds_f32(s1 + 4u * r_[2]) * fcw[r_[2]];
    }
#pragma unroll
    for (int m = 1; m < 8; m <<= 1) {
        p0 += __shfl_xor_sync(0xffffffffu, p0, m, 8);
        p1 += __shfl_xor_sync(0xffffffffu, p1, m, 8);
    }
    if (e == 0) {
        if (real0) out[b0] = p0 + fcb[0];
        if (real1) out[b1] = p1 + fcb[0];
    }
}

extern "C" void kernel_launch(void* const* d_in, const int* in_sizes, int n_in,
                              void* d_out, int out_size)
{
    const float* x    = (const float*)d_in[0];
    const float* Wih  = (const float*)d_in[1];
    const float* Whh  = (const float*)d_in[2];
    const float* bih  = (const float*)d_in[3];
    const float* bhh  = (const float*)d_in[4];
    const float* fcw  = (const float*)d_in[5];
    const float* fcb  = (const float*)d_in[6];
    float* out = (float*)d_out;

    int B = out_size;
    int T = in_sizes[0] / B;

    const int threads = 128;            // 4 warps -> one per SMSP
    int blocks = (B + 31) / 32;         // 32 batches/CTA -> 128 CTAs at B=4096
    rnn_fused_kernel<<<blocks, threads>>>(x, Wih, Whh, bih, bhh, fcw, fcb, out, B, T);
}

// round 12
// speedup vs baseline: 1.3901x; 1.1604x over previous
#include <cuda_runtime.h>

// RNN_33964601377372: h_{t+1} = relu(x_t*W_ih + b_ih + b_hh + W_hh h_t), out = fc(h_T)
//
// R8 geometry (best measured): L=8 row-split, 4 batches/warp, block=256 ->
// 2 warps/SMSP, grid=128. This round:
//  - no per-step syncwarp (same-warp in-order LSU ordering, validated R9)
//  - each row's dot product split into TWO 5-deep FFMA2 chains + FADD2
//    (critical path 40 -> 24 cyc, 6 independent chains per lane)
//  - warp-parity stagger: odd warps' h(0) depends on a one-off LDG*0.0f,
//    offsetting co-resident warps ~600 cyc so their stalls interleave.

#define HID 20

typedef unsigned long long u64;

__device__ __forceinline__ u64 pack2(float lo, float hi) {
    u64 r; asm("mov.b64 %0, {%1, %2};" : "=l"(r) : "f"(lo), "f"(hi)); return r;
}
__device__ __forceinline__ u64 dup2(float v) {
    u64 r; asm("mov.b64 %0, {%1, %1};" : "=l"(r) : "f"(v)); return r;
}
__device__ __forceinline__ void unpack2(u64 p, float& lo, float& hi) {
    asm("mov.b64 {%0, %1}, %2;" : "=f"(lo), "=f"(hi) : "l"(p));
}
__device__ __forceinline__ u64 ffma2(u64 a, u64 b, u64 c) {
    u64 d; asm("fma.rn.f32x2 %0, %1, %2, %3;" : "=l"(d) : "l"(a), "l"(b), "l"(c)); return d;
}
__device__ __forceinline__ u64 fmul2(u64 a, u64 b) {
    u64 d; asm("mul.rn.f32x2 %0, %1, %2;" : "=l"(d) : "l"(a), "l"(b)); return d;
}
__device__ __forceinline__ u64 fadd2(u64 a, u64 b) {
    u64 d; asm("add.rn.f32x2 %0, %1, %2;" : "=l"(d) : "l"(a), "l"(b)); return d;
}
__device__ __forceinline__ void lds_v2u64(unsigned addr, u64& a, u64& b) {
    asm volatile("ld.shared.v2.u64 {%0, %1}, [%2];" : "=l"(a), "=l"(b) : "r"(addr));
}
__device__ __forceinline__ void sts_f32(unsigned addr, float v) {
    asm volatile("st.shared.f32 [%0], %1;" :: "r"(addr), "f"(v));
}
__device__ __forceinline__ float lds_f32(unsigned addr) {
    float v; asm volatile("ld.shared.f32 %0, [%1];" : "=f"(v) : "r"(addr)); return v;
}

#define ROW_PAD 24   // floats per h row (96B): conflict-free 16B reads & stores

__global__ __launch_bounds__(256) void rnn_fused_kernel(
    const float* __restrict__ x,    // [B, T]
    const float* __restrict__ Wih,  // [H]
    const float* __restrict__ Whh,  // [H, H] row-major
    const float* __restrict__ bih,  // [H]
    const float* __restrict__ bhh,  // [H]
    const float* __restrict__ fcw,  // [H]
    const float* __restrict__ fcb,  // [1]
    float* __restrict__ out,        // [B]
    int B, int T)
{
    __shared__ float hbuf[32][ROW_PAD];

    const int lt  = threadIdx.x;
    const int wid = lt >> 5;           // warp within CTA (0..7)
    const int g   = lt >> 3;           // batch within CTA (0..31)
    const int e   = lt & 7;            // lane within batch group
    int batch = blockIdx.x * 32 + g;
    const bool real = (batch < B);
    if (!real) batch = B - 1;          // clamp; lane stays resident

    // Owned rows; lanes e>=4 duplicate row e as third (same value, same addr).
    const int r_[3] = { e, 8 + e, (e < 4) ? 16 + e : e };

    // j-packed weights: wJ[r][k] = (Whh[row][2k], Whh[row][2k+1])
    u64 wJ[3][10];
#pragma unroll
    for (int r = 0; r < 3; ++r)
#pragma unroll
        for (int k = 0; k < 10; ++k)
            wJ[r][k] = pack2(Whh[r_[r] * HID + 2 * k],
                             Whh[r_[r] * HID + 2 * k + 1]);

    u64 wihP[3], biasP[3];
#pragma unroll
    for (int r = 0; r < 3; ++r) {
        wihP[r]  = pack2(Wih[r_[r]], 0.0f);
        biasP[r] = pack2(bih[r_[r]] + bhh[r_[r]], 0.0f);
    }

    const unsigned sbase =
        (unsigned)__cvta_generic_to_shared(&hbuf[g][0]);   // 96B stride

    const float* xb = x + (size_t)batch * T;    // 4000B stride, 16B-aligned
    const float4* xb4 = (const float4*)xb;
    const int nChunks = T >> 2;                 // 250 for T=1000

    // Warp-parity stagger: odd warps' h(0) store depends on a one-off DRAM
    // load (value-neutral: *0.0f, x is finite), delaying them ~600 cyc so the
    // SMSP's two warps run out of phase for the whole barrier-free loop.
    float stag = 0.0f;
    if (wid & 1) stag = xb[T >> 1] * 0.0f;

    // h(0) = 0 (+stag==0); subsequent same-warp LDS see it in program order.
#pragma unroll
    for (int r = 0; r < 3; ++r) sts_f32(sbase + 4u * r_[r], stag);

    auto step = [&](float xt) {
        u64 hp[10];
#pragma unroll
        for (int i = 0; i < 5; ++i)
            lds_v2u64(sbase + 16u * i, hp[2 * i], hp[2 * i + 1]);

        u64 xt2 = dup2(xt);
        u64 accA[3], accB[3];
#pragma unroll
        for (int r = 0; r < 3; ++r)
            accA[r] = ffma2(xt2, wihP[r], biasP[r]);   // independent of LDS
#pragma unroll
        for (int r = 0; r < 3; ++r)
            accB[r] = fmul2(hp[5], wJ[r][5]);
#pragma unroll
        for (int k = 0; k < 5; ++k)
#pragma unroll
            for (int r = 0; r < 3; ++r)
                accA[r] = ffma2(hp[k], wJ[r][k], accA[r]);
#pragma unroll
        for (int k = 6; k < 10; ++k)
#pragma unroll
            for (int r = 0; r < 3; ++r)
                accB[r] = ffma2(hp[k], wJ[r][k], accB[r]);

#pragma unroll
        for (int r = 0; r < 3; ++r) {
            u64 s = fadd2(accA[r], accB[r]);
            float lo, hi;
            unpack2(s, lo, hi);
            sts_f32(sbase + 4u * r_[r], fmaxf(lo + hi, 0.0f));
        }
    };

    // Deep x prefetch: 2 chunks (8 steps) in flight.
    float4 x0 = make_float4(0.f, 0.f, 0.f, 0.f);
    float4 x1 = x0;
    if (nChunks > 0) x0 = xb4[0];
    if (nChunks > 1) x1 = xb4[1];

    for (int c = 0; c < nChunks; ++c) {
        float4 x2 = x1;
        if (c + 2 < nChunks) x2 = xb4[c + 2];
        step(x0.x);
        step(x0.y);
        step(x0.z);
        step(x0.w);
        x0 = x1;
        x1 = x2;
    }
    for (int t = nChunks << 2; t < T; ++t) step(xb[t]);  // tail (unused @T=1000)

    __syncwarp();   // one-time: publish final h for head reads

    // Head: out[b] = h . fc_w + fc_b over owned rows (dummy masked), then
    // xor-reduce across the 8-lane group.
    float p = lds_f32(sbase + 4u * r_[0]) * fcw[r_[0]]
            + lds_f32(sbase + 4u * r_[1]) * fcw[r_[1]];
    if (e < 4) p += lds_f32(sbase + 4u * r_[2]) * fcw[r_[2]];
    p += __shfl_xor_sync(0xffffffffu, p, 1, 8);
    p += __shfl_xor_sync(0xffffffffu, p, 2, 8);
    p += __shfl_xor_sync(0xffffffffu, p, 4, 8);
    if (e == 0 && real) out[batch] = p + fcb[0];
}

extern "C" void kernel_launch(void* const* d_in, const int* in_sizes, int n_in,
                              void* d_out, int out_size)
{
    const float* x    = (const float*)d_in[0];
    const float* Wih  = (const float*)d_in[1];
    const float* Whh  = (const float*)d_in[2];
    const float* bih  = (const float*)d_in[3];
    const float* bhh  = (const float*)d_in[4];
    const float* fcw  = (const float*)d_in[5];
    const float* fcb  = (const float*)d_in[6];
    float* out = (float*)d_out;

    int B = out_size;
    int T = in_sizes[0] / B;

    const int threads = 256;            // 8 warps -> 2 per SMSP; 32 batches/CTA
    int blocks = (B + 31) / 32;         // 128 CTAs at B=4096
    rnn_fused_kernel<<<blocks, threads>>>(x, Wih, Whh, bih, bhh, fcw, fcb, out, B, T);
}

// round 13
// speedup vs baseline: 1.4389x; 1.0351x over previous
#include <cuda_runtime.h>

// RNN_33964601377372: h_{t+1} = relu(x_t*W_ih + b_ih + b_hh + W_hh h_t), out = fc(h_T)
//
// R8 geometry, SCALAR math. Diagnosis across 12 rounds: packed fma.rn.f32x2
// chains show ~10-12 cyc RAW latency (every packed kernel latency-pins at
// ~208-230 cyc/step regardless of slot count, while scalar R1 was exactly
// issue-bound). This kernel: L=8 row-split (lane e owns rows {e, 8+e,
// (e<4)?16+e:e}; dummy third row for e>=4 is a harmless duplicate), h in
// per-warp smem with NO per-step sync (same-warp in-order LSU, validated R9),
// gather = 5x ld.shared.v4.f32 -> 20 plain float regs (zero pack/dup ops),
// 3 independent 20-deep scalar FFMA chains per lane (lat 4), x-proj seeds
// issued before the gather. block=256 -> 2 warps/SMSP; grid=128 -> 1 CTA/SM.

#define HID 20

__device__ __forceinline__ void lds_v4f32(unsigned addr, float& a, float& b,
                                          float& c, float& d) {
    asm volatile("ld.shared.v4.f32 {%0, %1, %2, %3}, [%4];"
                 : "=f"(a), "=f"(b), "=f"(c), "=f"(d) : "r"(addr));
}
__device__ __forceinline__ void sts_f32(unsigned addr, float v) {
    asm volatile("st.shared.f32 [%0], %1;" :: "r"(addr), "f"(v));
}
__device__ __forceinline__ float lds_f32(unsigned addr) {
    float v; asm volatile("ld.shared.f32 %0, [%1];" : "=f"(v) : "r"(addr)); return v;
}

#define ROW_PAD 24   // floats per h row (96B): conflict-free 16B reads & stores

__global__ __launch_bounds__(256) void rnn_fused_kernel(
    const float* __restrict__ x,    // [B, T]
    const float* __restrict__ Wih,  // [H]
    const float* __restrict__ Whh,  // [H, H] row-major
    const float* __restrict__ bih,  // [H]
    const float* __restrict__ bhh,  // [H]
    const float* __restrict__ fcw,  // [H]
    const float* __restrict__ fcb,  // [1]
    float* __restrict__ out,        // [B]
    int B, int T)
{
    __shared__ float hbuf[32][ROW_PAD];

    const int lt = threadIdx.x;
    const int g  = lt >> 3;            // batch within CTA (0..31)
    const int e  = lt & 7;             // lane within batch group
    int batch = blockIdx.x * 32 + g;
    const bool real = (batch < B);
    if (!real) batch = B - 1;          // clamp; lane stays resident

    // Owned rows; lanes e>=4 duplicate row e as third (same value, same addr).
    const int r_[3] = { e, 8 + e, (e < 4) ? 16 + e : e };

    // Scalar weights for my 3 rows.
    float wS[3][HID];
#pragma unroll
    for (int r = 0; r < 3; ++r)
#pragma unroll
        for (int j = 0; j < HID; ++j)
            wS[r][j] = Whh[r_[r] * HID + j];

    float wih[3], bias[3];
#pragma unroll
    for (int r = 0; r < 3; ++r) {
        wih[r]  = Wih[r_[r]];
        bias[r] = bih[r_[r]] + bhh[r_[r]];
    }

    const unsigned sbase =
        (unsigned)__cvta_generic_to_shared(&hbuf[g][0]);   // 96B stride

    // h(0) = 0; later same-warp LDS observe it in program order.
#pragma unroll
    for (int r = 0; r < 3; ++r) sts_f32(sbase + 4u * r_[r], 0.0f);

    const float* xb = x + (size_t)batch * T;    // 4000B stride, 16B-aligned
    const float4* xb4 = (const float4*)xb;
    const int nChunks = T >> 2;                 // 250 for T=1000

    auto step = [&](float xt) {
        // Independent seeds first: fill the LDS-return window.
        float acc[3];
#pragma unroll
        for (int r = 0; r < 3; ++r)
            acc[r] = fmaf(xt, wih[r], bias[r]);

        // Gather h_t: 5 vector loads -> 20 scalar float regs, no pack ops.
        float h[HID];
#pragma unroll
        for (int i = 0; i < 5; ++i)
            lds_v4f32(sbase + 16u * i,
                      h[4 * i], h[4 * i + 1], h[4 * i + 2], h[4 * i + 3]);

        // 3 independent 20-deep scalar FFMA chains (lat 4, rt 2).
#pragma unroll
        for (int j = 0; j < HID; ++j)
#pragma unroll
            for (int r = 0; r < 3; ++r)
                acc[r] = fmaf(h[j], wS[r][j], acc[r]);

#pragma unroll
        for (int r = 0; r < 3; ++r)
            sts_f32(sbase + 4u * r_[r], fmaxf(acc[r], 0.0f));
    };

    // Deep x prefetch: 2 chunks (8 steps) in flight.
    float4 x0 = make_float4(0.f, 0.f, 0.f, 0.f);
    float4 x1 = x0;
    if (nChunks > 0) x0 = xb4[0];
    if (nChunks > 1) x1 = xb4[1];

    for (int c = 0; c < nChunks; ++c) {
        float4 x2 = x1;
        if (c + 2 < nChunks) x2 = xb4[c + 2];
        step(x0.x);
        step(x0.y);
        step(x0.z);
        step(x0.w);
        x0 = x1;
        x1 = x2;
    }
    for (int t = nChunks << 2; t < T; ++t) step(xb[t]);  // tail (unused @T=1000)

    __syncwarp();   // one-time: publish final h for head reads

    // Head: out[b] = h . fc_w + fc_b over owned rows (dummy masked), then
    // xor-reduce across the 8-lane group.
    float p = lds_f32(sbase + 4u * r_[0]) * fcw[r_[0]]
            + lds_f32(sbase + 4u * r_[1]) * fcw[r_[1]];
    if (e < 4) p += lds_f32(sbase + 4u * r_[2]) * fcw[r_[2]];
    p += __shfl_xor_sync(0xffffffffu, p, 1, 8);
    p += __shfl_xor_sync(0xffffffffu, p, 2, 8);
    p += __shfl_xor_sync(0xffffffffu, p, 4, 8);
    if (e == 0 && real) out[batch] = p + fcb[0];
}

extern "C" void kernel_launch(void* const* d_in, const int* in_sizes, int n_in,
                              void* d_out, int out_size)
{
    const float* x    = (const float*)d_in[0];
    const float* Wih  = (const float*)d_in[1];
    const float* Whh  = (const float*)d_in[2];
    const float* bih  = (const float*)d_in[3];
    const float* bhh  = (const float*)d_in[4];
    const float* fcw  = (const float*)d_in[5];
    const float* fcb  = (const float*)d_in[6];
    float* out = (float*)d_out;

    int B = out_size;
    int T = in_sizes[0] / B;

    const int threads = 256;            // 8 warps -> 2 per SMSP; 32 batches/CTA
    int blocks = (B + 31) / 32;         // 128 CTAs at B=4096
    rnn_fused_kernel<<<blocks, threads>>>(x, Wih, Whh, bih, bhh, fcw, fcb, out, B, T);
}